// round 13
// baseline (speedup 1.0000x reference)
#include <cuda_runtime.h>

#define B_ROWS 16384
#define HID 256
#define COMP 32
#define T_TOK 8
#define NVOC 257
#define VSTRIDE 261          // padded row stride for sorted vocab (bank-spread)
#define NF 0.0625f
#define EPS_THR 1e-6f
#define NGROUP 2048
#define ROWS_PB 16

typedef unsigned long long u64;

// ---- packed fp32x2 helpers (sm_103a FFMA2 path; ptxas never auto-fuses) ----
__device__ __forceinline__ u64 pk(float lo, float hi) {
    u64 r; asm("mov.b64 %0,{%1,%2};" : "=l"(r) : "f"(lo), "f"(hi)); return r;
}
__device__ __forceinline__ void ffma2(u64& d, u64 a, u64 b) {
    asm("fma.rn.f32x2 %0,%1,%2,%0;" : "+l"(d) : "l"(a), "l"(b));
}
__device__ __forceinline__ float upk_sum(u64 v) {
    float lo, hi; asm("mov.b64 {%0,%1},%2;" : "=f"(lo), "=f"(hi) : "l"(v));
    return lo + hi;
}
// one LDS.128 -> two packed f32x2 operands, no pack MOVs
__device__ __forceinline__ void lds2(u64& a, u64& b, unsigned addr) {
    asm("ld.shared.v2.u64 {%0,%1},[%2];" : "=l"(a), "=l"(b) : "r"(addr));
}

// ---------------- device scratch (no allocations allowed) ----------------
__device__ float g_msg[B_ROWS * HID];
__device__ float g_vocs[COMP * VSTRIDE];   // per-dim sorted vocab columns
__device__ float g_Wf[HID * HID];          // W_sum @ W_head
__device__ float g_bf[HID];                // b_sum @ W_head + b_head

// ---------------- Kernel 0: prep (sort vocab | fuse tail weights) ---------
// grid 160 x 512 threads. blocks 0-31: bitonic sort of vocab dim b.
// blocks 32-159: 2 rows of Wf = Wsum@Whead each (128 GEMM blocks run
// concurrently with the 32 sort blocks); block 159 also computes bf.
__global__ __launch_bounds__(512) void prep_kernel(
    const float* __restrict__ vocab,
    const float* __restrict__ Wsum, const float* __restrict__ bsum,
    const float* __restrict__ Whead, const float* __restrict__ bhead)
{
    const int b = blockIdx.x;
    const int t = threadIdx.x;
    if (b < 32) {
        __shared__ float buf[512];
        const int d = b;
        buf[t] = (t < NVOC) ? vocab[t * COMP + d] : 1e30f;
        __syncthreads();
        for (int k = 2; k <= 512; k <<= 1) {
            for (int j = k >> 1; j > 0; j >>= 1) {
                int ixj = t ^ j;
                if (ixj > t) {
                    float a = buf[t], bb = buf[ixj];
                    bool up = ((t & k) == 0);
                    if ((a > bb) == up) { buf[t] = bb; buf[ixj] = a; }
                }
                __syncthreads();
            }
        }
        if (t < NVOC) g_vocs[d * VSTRIDE + t] = buf[t];
    } else {
        __shared__ float Ws[2 * HID];
        const int rbase = (b - 32) * 2;            // 2 Wf rows per block
        for (int i = t; i < 2 * HID; i += 512)
            Ws[i] = Wsum[rbase * HID + i];
        __syncthreads();
        const int rl = t >> 8;                     // local row 0/1
        const int c  = t & 255;
        const float* wsr = Ws + rl * HID;
        float acc = 0.f;
        #pragma unroll 8
        for (int k = 0; k < HID; k++)
            acc += wsr[k] * Whead[k * HID + c];
        g_Wf[(rbase + rl) * HID + c] = acc;
        if (b == 159 && t < HID) {
            float s0 = 0.f, s1 = 0.f, s2 = 0.f, s3 = 0.f;
            #pragma unroll 2
            for (int j = 0; j < HID; j += 4) {
                s0 += bsum[j + 0] * Whead[(j + 0) * HID + t];
                s1 += bsum[j + 1] * Whead[(j + 1) * HID + t];
                s2 += bsum[j + 2] * Whead[(j + 2) * HID + t];
                s3 += bsum[j + 3] * Whead[(j + 3) * HID + t];
            }
            g_bf[t] = bhead[t] + ((s0 + s1) + (s2 + s3));
        }
    }
}

// branchless lower-bound nearest-neighbor squared distance (bitwise identical
// to the full 257-entry per-dim min scan; see round-2 derivation).
__device__ __forceinline__ float nearest_sq(const float* __restrict__ arr, float x)
{
    int p = 0;
    #pragma unroll
    for (int s = 256; s; s >>= 1) {
        int q = p + s;
        if (q <= NVOC) { if (arr[q - 1] <= x) p = q; }
    }
    float lo = (p > 0)    ? arr[p - 1] : 1e30f;
    float hi = (p < NVOC) ? arr[p]     : 1e30f;
    float a = x - lo, b = x - hi;
    return fminf(a * a, b * b);
}

// ---------------- Kernel 1: persistent fused main kernel -------------------
// R3 operand routing exactly; 16 rows/block, 256 threads, 2 blocks/SM.
// smem (floats):
//   ha_s   [16*256]   0     (hs tile; e*V per iter; kp staging)
//   msg_s  [16*256]   4096
//   vocs_s [32*261]   8192
//   tok_s  [16*32]    16544
//   eos_s  [32]       17056
//   maskf  [16]       17088
//   fin_s  [16]       17104
//   part_s [16*8]     17120
// total 17248 floats = 68992 B, x2 = 138 KB/SM.
__global__ void __launch_bounds__(256, 2) main_kernel(
    const float* __restrict__ hs,
    const float* __restrict__ WQ, const float* __restrict__ bQ,
    const float* __restrict__ WK, const float* __restrict__ bK,
    const float* __restrict__ Wmu, const float* __restrict__ bmu,
    const float* __restrict__ Wvar, const float* __restrict__ bvar,
    const float* __restrict__ vocab, const float* __restrict__ eps)
{
    extern __shared__ float sm[];
    float* ha_s   = sm;
    float* msg_s  = sm + 4096;
    float* vocs_s = sm + 8192;
    float* tok_s  = sm + 16544;
    float* eos_s  = sm + 17056;
    float* maskf  = sm + 17088;
    float* fin_s  = sm + 17104;
    float* part_s = sm + 17120;

    const int t = threadIdx.x;
    const int r0 = blockIdx.x * ROWS_PB;
    const int w = t >> 5, l = t & 31;
    const unsigned ha_sa  = (unsigned)__cvta_generic_to_shared(ha_s);
    const unsigned tok_sa = (unsigned)__cvta_generic_to_shared(tok_s);

    // ---- block-resident setup ----
    for (int i = t; i < COMP * VSTRIDE; i += 256) vocs_s[i] = g_vocs[i];
    if (t < COMP) eos_s[t] = vocab[256 * COMP + t];
    if (t < ROWS_PB) { maskf[t] = 1.0f; fin_s[t] = 0.0f; }
    {
        const float4* src = (const float4*)(hs + (size_t)r0 * HID);
        float4* dst = (float4*)ha_s;
        #pragma unroll
        for (int i = 0; i < 4; i++) dst[t + i * 256] = src[t + i * 256];
    }
    __syncthreads();

    // ---- Q = (hs@WQ+bQ)*NF ; V = hs@WK+bK  (packed FFMA2 GEMM) ----
    float Qr[16], Vr[16], kacc[16];
    {
        const float bq = bQ[t], bk = bK[t];
        u64 aq[16], av[16];
        #pragma unroll
        for (int m = 0; m < 16; m++) { aq[m] = pk(bq, 0.0f); av[m] = pk(bk, 0.0f); }
        #pragma unroll 2
        for (int k = 0; k < HID; k += 4) {
            float q0 = WQ[(k+0)*HID+t], q1 = WQ[(k+1)*HID+t];
            float q2 = WQ[(k+2)*HID+t], q3 = WQ[(k+3)*HID+t];
            float v0 = WK[(k+0)*HID+t], v1 = WK[(k+1)*HID+t];
            float v2 = WK[(k+2)*HID+t], v3 = WK[(k+3)*HID+t];
            u64 wq01 = pk(q0, q1), wq23 = pk(q2, q3);
            u64 wv01 = pk(v0, v1), wv23 = pk(v2, v3);
            #pragma unroll
            for (int m = 0; m < 16; m++) {
                u64 a01, a23;
                lds2(a01, a23, ha_sa + (unsigned)((m * HID + k) * 4));
                ffma2(aq[m], a01, wq01); ffma2(aq[m], a23, wq23);
                ffma2(av[m], a01, wv01); ffma2(av[m], a23, wv23);
            }
        }
        #pragma unroll
        for (int m = 0; m < 16; m++) {
            Qr[m] = upk_sum(aq[m]) * NF;
            Vr[m] = upk_sum(av[m]);
            kacc[m] = bk;
        }
    }

    // ---- token recurrence (4 barriers/iter) ----
    #pragma unroll 1
    for (int it = 0; it < T_TOK; it++) {
        __syncthreads();   // A: orders prev-iter writes (tok/msg/mask/fin)

        // Phase 1: incremental K update with previous token (32 new msg cols)
        if (it > 0) {
            const float* wkp = WK + (size_t)((it - 1) * COMP) * HID + t;
            u64 acc2[16];
            #pragma unroll
            for (int m = 0; m < 16; m++) acc2[m] = 0ull;
            #pragma unroll
            for (int c = 0; c < COMP; c += 4) {
                float w0 = wkp[(c+0)*HID], w1 = wkp[(c+1)*HID];
                float w2 = wkp[(c+2)*HID], w3 = wkp[(c+3)*HID];
                u64 w01 = pk(w0, w1), w23 = pk(w2, w3);
                #pragma unroll
                for (int m = 0; m < 16; m++) {
                    u64 a01, a23;
                    lds2(a01, a23, tok_sa + (unsigned)((m * COMP + c) * 4));
                    ffma2(acc2[m], a01, w01); ffma2(acc2[m], a23, w23);
                }
            }
            #pragma unroll
            for (int m = 0; m < 16; m++) kacc[m] += upk_sum(acc2[m]);
        }

        // Phase 2: e = exp(-(Q*K)); write e*V to ha_s; per-row partial sums
        #pragma unroll
        for (int m = 0; m < 16; m++) {
            float e = __expf(-(Qr[m] * (kacc[m] * NF)));
            ha_s[m * HID + t] = e * Vr[m];
            float s = e;
            #pragma unroll
            for (int o = 16; o; o >>= 1) s += __shfl_xor_sync(0xffffffffu, s, o);
            if (l == 0) part_s[m * 8 + w] = s;
        }
        __syncthreads();   // B: ha_s + part_s visible

        // Phase 3a: raw (e*V) @ [Wmu|Wvar], packed FFMA2; thread owns 1 output
        // col for all 16 rows over a 64-wide k-partition (weights LDG x16 reuse)
        {
            const int c  = t & 63;
            const int kp = t >> 6;
            const float* Wcol = (c < 32) ? (Wmu + c) : (Wvar + (c - 32));
            const int k0 = kp * 64;
            u64 acc2[16];
            #pragma unroll
            for (int m = 0; m < 16; m++) acc2[m] = 0ull;
            #pragma unroll 2
            for (int k = k0; k < k0 + 64; k += 4) {
                float w0 = Wcol[(size_t)(k+0)*COMP], w1 = Wcol[(size_t)(k+1)*COMP];
                float w2 = Wcol[(size_t)(k+2)*COMP], w3 = Wcol[(size_t)(k+3)*COMP];
                u64 w01 = pk(w0, w1), w23 = pk(w2, w3);
                #pragma unroll
                for (int m = 0; m < 16; m++) {
                    u64 a01, a23;
                    lds2(a01, a23, ha_sa + (unsigned)((m * HID + k) * 4));
                    ffma2(acc2[m], a01, w01); ffma2(acc2[m], a23, w23);
                }
            }
            __syncthreads();   // D: all ha_s reads done -> reuse as staging
            #pragma unroll
            for (int m = 0; m < 16; m++)
                ha_s[kp * 1024 + m * 64 + c] = upk_sum(acc2[m]);
        }
        __syncthreads();   // E: staging visible

        // Phase 3b+4 merged: kp-reduce + normalize + sample + nearest-vocab,
        // then EOS/repeat-hit via HALF-WARP shfls (row m = 16 lanes), no barrier
        {
            const int m  = t >> 4;
            const int q  = t & 15;
            const int q2 = q * 2;
            float smu0 = 0.0f, smu1 = 0.0f, slv0 = 0.0f, slv1 = 0.0f;
            #pragma unroll
            for (int kp = 0; kp < 4; kp++) {
                float2 a = *(const float2*)&ha_s[kp * 1024 + m * 64 + q2];
                float2 b = *(const float2*)&ha_s[kp * 1024 + m * 64 + 32 + q2];
                smu0 += a.x; smu1 += a.y;
                slv0 += b.x; slv1 += b.y;
            }
            float rs = 0.0f;
            #pragma unroll
            for (int ww = 0; ww < 8; ww++) rs += part_s[m * 8 + ww];
            const float iv = 1.0f / rs;
            float2 bm = *(const float2*)&bmu[q2];
            float2 bv = *(const float2*)&bvar[q2];
            float mu0 = smu0 * iv + bm.x, mu1 = smu1 * iv + bm.y;
            float lv0 = slv0 * iv + bv.x, lv1 = slv1 * iv + bv.y;
            const size_t r = (size_t)(r0 + m);
            float2 e2 = *(const float2*)&eps[((size_t)it * B_ROWS + r) * COMP + q2];
            float x0 = e2.x * __expf(0.5f * lv0) + mu0;
            float x1 = e2.y * __expf(0.5f * lv1) + mu1;
            const float mk = maskf[m];
            float t0 = nearest_sq(vocs_s + q2 * VSTRIDE, x0) * mk;
            float t1 = nearest_sq(vocs_s + (q2 + 1) * VSTRIDE, x1) * mk;

            // EOS hit (half-warp reduce over 16 lanes x 2 comps)
            float2 ev = *(const float2*)&eos_s[q2];
            float de0 = t0 - ev.x, de1 = t1 - ev.y;
            float se = de0 * de0 + de1 * de1;
            #pragma unroll
            for (int o = 8; o; o >>= 1) se += __shfl_xor_sync(0xffffffffu, se, o);
            bool hit = (se < EPS_THR);
            // previous-token hits
            for (int p = 0; p < it; p++) {
                float2 mp = *(const float2*)&msg_s[m * HID + p * COMP + q2];
                float d0 = t0 - mp.x, d1 = t1 - mp.y;
                float sp = d0 * d0 + d1 * d1;
                #pragma unroll
                for (int o = 8; o; o >>= 1) sp += __shfl_xor_sync(0xffffffffu, sp, o);
                hit = hit || (sp < EPS_THR);
            }
            float fin = fin_s[m];
            bool new_eos = hit && (fin == 0.0f);
            float o0 = new_eos ? ev.x : t0;
            float o1 = new_eos ? ev.y : t1;
            *(float2*)&msg_s[m * HID + it * COMP + q2] = make_float2(o0, o1);
            *(float2*)&tok_s[m * COMP + q2] = make_float2(o0, o1);
            if (q == 0 && hit) { maskf[m] = 0.0f; fin_s[m] = 1.0f; }
        }
    }

    // ---- flush message to global for the tail ----
    __syncthreads();
    {
        float4* dst = (float4*)(g_msg + (size_t)r0 * HID);
        const float4* src = (const float4*)msg_s;
        #pragma unroll
        for (int i = 0; i < 4; i++) dst[t + i * 256] = src[t + i * 256];
    }
}

// ---------------- Kernel 2: fused tail: relu(groupsum/7 @ Wf + bf) --------
// single GEMM thanks to precomputed Wf = Wsum@Whead. 8 groups/block, grid 256.
__global__ __launch_bounds__(256) void tail_kernel(float* __restrict__ out)
{
    __shared__ __align__(16) float A_s[8 * HID];
    const int t = threadIdx.x;
    const int g0 = blockIdx.x * 8;
    const unsigned A_sa = (unsigned)__cvta_generic_to_shared(A_s);

    #pragma unroll
    for (int m = 0; m < 8; m++) {
        float s = 0.0f;
        #pragma unroll
        for (int a = 0; a < 8; a++)
            s += g_msg[(size_t)((g0 + m) * 8 + a) * HID + t];
        A_s[m * HID + t] = s * (1.0f / 7.0f);
    }
    __syncthreads();

    u64 acc2[8];
    const float bb = g_bf[t];
    #pragma unroll
    for (int m = 0; m < 8; m++) acc2[m] = pk(bb, 0.0f);
    #pragma unroll 2
    for (int k = 0; k < HID; k += 4) {
        float w0 = g_Wf[(k+0)*HID+t], w1 = g_Wf[(k+1)*HID+t];
        float w2 = g_Wf[(k+2)*HID+t], w3 = g_Wf[(k+3)*HID+t];
        u64 w01 = pk(w0, w1), w23 = pk(w2, w3);
        #pragma unroll
        for (int m = 0; m < 8; m++) {
            u64 a01, a23;
            lds2(a01, a23, A_sa + (unsigned)((m * HID + k) * 4));
            ffma2(acc2[m], a01, w01); ffma2(acc2[m], a23, w23);
        }
    }
    #pragma unroll
    for (int m = 0; m < 8; m++) {
        float v = fmaxf(upk_sum(acc2[m]), 0.0f);
        #pragma unroll
        for (int a = 0; a < 8; a++)
            out[(size_t)((g0 + m) * 8 + a) * HID + t] = v;
    }
}

// ---------------- launch ---------------------------------------------------
extern "C" void kernel_launch(void* const* d_in, const int* in_sizes, int n_in,
                              void* d_out, int out_size)
{
    const float* hs    = (const float*)d_in[0];
    const float* eps   = (const float*)d_in[1];
    const float* WQ    = (const float*)d_in[2];
    const float* bQ    = (const float*)d_in[3];
    const float* WK    = (const float*)d_in[4];
    const float* bK    = (const float*)d_in[5];
    const float* Wmu   = (const float*)d_in[6];
    const float* bmu   = (const float*)d_in[7];
    const float* Wvar  = (const float*)d_in[8];
    const float* bvar  = (const float*)d_in[9];
    const float* vocab = (const float*)d_in[10];
    const float* Wsum  = (const float*)d_in[11];
    const float* bsum  = (const float*)d_in[12];
    const float* Whead = (const float*)d_in[13];
    const float* bhead = (const float*)d_in[14];
    float* out = (float*)d_out;

    const int smem_main = 17248 * (int)sizeof(float);   // 68992 B
    cudaFuncSetAttribute(main_kernel,
                         cudaFuncAttributeMaxDynamicSharedMemorySize, smem_main);

    prep_kernel<<<160, 512>>>(vocab, Wsum, bsum, Whead, bhead);
    main_kernel<<<B_ROWS / ROWS_PB, 256, smem_main>>>(
        hs, WQ, bQ, WK, bK, Wmu, bmu, Wvar, bvar, vocab, eps);
    tail_kernel<<<NGROUP / 8, 256>>>(out);
}

// round 14
// speedup vs baseline: 1.5687x; 1.5687x over previous
#include <cuda_runtime.h>

#define B_ROWS 16384
#define HID 256
#define COMP 32
#define T_TOK 8
#define NVOC 257
#define VSTRIDE 261          // padded row stride for sorted vocab (bank-spread)
#define NF 0.0625f
#define EPS_THR 1e-6f
#define NGROUP 2048
#define ROWS_PB 16

typedef unsigned long long u64;

// ---- packed fp32x2 helpers (sm_103a FFMA2 path; ptxas never auto-fuses) ----
__device__ __forceinline__ u64 pk(float lo, float hi) {
    u64 r; asm("mov.b64 %0,{%1,%2};" : "=l"(r) : "f"(lo), "f"(hi)); return r;
}
__device__ __forceinline__ void ffma2(u64& d, u64 a, u64 b) {
    asm("fma.rn.f32x2 %0,%1,%2,%0;" : "+l"(d) : "l"(a), "l"(b));
}
__device__ __forceinline__ float upk_sum(u64 v) {
    float lo, hi; asm("mov.b64 {%0,%1},%2;" : "=f"(lo), "=f"(hi) : "l"(v));
    return lo + hi;
}
// one LDS.128 -> two packed f32x2 operands, no pack MOVs
__device__ __forceinline__ void lds2(u64& a, u64& b, unsigned addr) {
    asm("ld.shared.v2.u64 {%0,%1},[%2];" : "=l"(a), "=l"(b) : "r"(addr));
}

// ---------------- device scratch (no allocations allowed) ----------------
__device__ float g_msg[B_ROWS * HID];
__device__ float g_vocs[COMP * VSTRIDE];   // per-dim sorted vocab columns

// ---------------- Kernel 0: per-dim bitonic sort of vocab columns ---------
__global__ __launch_bounds__(512) void sort_kernel(const float* __restrict__ vocab)
{
    __shared__ float buf[512];
    const int d = blockIdx.x;
    const int t = threadIdx.x;
    buf[t] = (t < NVOC) ? vocab[t * COMP + d] : 1e30f;
    __syncthreads();
    for (int k = 2; k <= 512; k <<= 1) {
        for (int j = k >> 1; j > 0; j >>= 1) {
            int ixj = t ^ j;
            if (ixj > t) {
                float a = buf[t], b = buf[ixj];
                bool up = ((t & k) == 0);
                if ((a > b) == up) { buf[t] = b; buf[ixj] = a; }
            }
            __syncthreads();
        }
    }
    if (t < NVOC) g_vocs[d * VSTRIDE + t] = buf[t];
}

// branchless lower-bound nearest-neighbor squared distance (bitwise identical
// to the full 257-entry per-dim min scan; see round-2 derivation).
__device__ __forceinline__ float nearest_sq(const float* __restrict__ arr, float x)
{
    int p = 0;
    #pragma unroll
    for (int s = 256; s; s >>= 1) {
        int q = p + s;
        if (q <= NVOC) { if (arr[q - 1] <= x) p = q; }
    }
    float lo = (p > 0)    ? arr[p - 1] : 1e30f;
    float hi = (p < NVOC) ? arr[p]     : 1e30f;
    float a = x - lo, b = x - hi;
    return fminf(a * a, b * b);
}

// ---------------- Kernel 1: persistent fused main kernel -------------------
// Byte-identical to the 477us configuration (R9). 16 rows/block, 256 threads,
// 2 blocks/SM. smem (floats):
//   ha_s   [16*256]   0     (hs tile; e*V per iter; kp staging)
//   msg_s  [16*256]   4096
//   vocs_s [32*261]   8192
//   tok_s  [16*32]    16544
//   eos_s  [32]       17056
//   maskf  [16]       17088
//   fin_s  [16]       17104
//   part_s [16*8]     17120
// total 17248 floats = 68992 B, x2 = 138 KB/SM.
__global__ void __launch_bounds__(256, 2) main_kernel(
    const float* __restrict__ hs,
    const float* __restrict__ WQ, const float* __restrict__ bQ,
    const float* __restrict__ WK, const float* __restrict__ bK,
    const float* __restrict__ Wmu, const float* __restrict__ bmu,
    const float* __restrict__ Wvar, const float* __restrict__ bvar,
    const float* __restrict__ vocab, const float* __restrict__ eps)
{
    extern __shared__ float sm[];
    float* ha_s   = sm;
    float* msg_s  = sm + 4096;
    float* vocs_s = sm + 8192;
    float* tok_s  = sm + 16544;
    float* eos_s  = sm + 17056;
    float* maskf  = sm + 17088;
    float* fin_s  = sm + 17104;
    float* part_s = sm + 17120;

    const int t = threadIdx.x;
    const int r0 = blockIdx.x * ROWS_PB;
    const int w = t >> 5, l = t & 31;
    const unsigned ha_sa  = (unsigned)__cvta_generic_to_shared(ha_s);
    const unsigned tok_sa = (unsigned)__cvta_generic_to_shared(tok_s);

    // ---- block-resident setup ----
    for (int i = t; i < COMP * VSTRIDE; i += 256) vocs_s[i] = g_vocs[i];
    if (t < COMP) eos_s[t] = vocab[256 * COMP + t];
    if (t < ROWS_PB) { maskf[t] = 1.0f; fin_s[t] = 0.0f; }
    {
        const float4* src = (const float4*)(hs + (size_t)r0 * HID);
        float4* dst = (float4*)ha_s;
        #pragma unroll
        for (int i = 0; i < 4; i++) dst[t + i * 256] = src[t + i * 256];
    }
    __syncthreads();

    // ---- Q = (hs@WQ+bQ)*NF ; V = hs@WK+bK  (packed FFMA2 GEMM) ----
    float Qr[16], Vr[16], kacc[16];
    {
        const float bq = bQ[t], bk = bK[t];
        u64 aq[16], av[16];
        #pragma unroll
        for (int m = 0; m < 16; m++) { aq[m] = pk(bq, 0.0f); av[m] = pk(bk, 0.0f); }
        #pragma unroll 2
        for (int k = 0; k < HID; k += 4) {
            float q0 = WQ[(k+0)*HID+t], q1 = WQ[(k+1)*HID+t];
            float q2 = WQ[(k+2)*HID+t], q3 = WQ[(k+3)*HID+t];
            float v0 = WK[(k+0)*HID+t], v1 = WK[(k+1)*HID+t];
            float v2 = WK[(k+2)*HID+t], v3 = WK[(k+3)*HID+t];
            u64 wq01 = pk(q0, q1), wq23 = pk(q2, q3);
            u64 wv01 = pk(v0, v1), wv23 = pk(v2, v3);
            #pragma unroll
            for (int m = 0; m < 16; m++) {
                u64 a01, a23;
                lds2(a01, a23, ha_sa + (unsigned)((m * HID + k) * 4));
                ffma2(aq[m], a01, wq01); ffma2(aq[m], a23, wq23);
                ffma2(av[m], a01, wv01); ffma2(av[m], a23, wv23);
            }
        }
        #pragma unroll
        for (int m = 0; m < 16; m++) {
            Qr[m] = upk_sum(aq[m]) * NF;
            Vr[m] = upk_sum(av[m]);
            kacc[m] = bk;
        }
    }

    // ---- token recurrence (4 barriers/iter) ----
    #pragma unroll 1
    for (int it = 0; it < T_TOK; it++) {
        __syncthreads();   // A: orders prev-iter writes (tok/msg/mask/fin)

        // Phase 1: incremental K update with previous token (32 new msg cols)
        if (it > 0) {
            const float* wkp = WK + (size_t)((it - 1) * COMP) * HID + t;
            u64 acc2[16];
            #pragma unroll
            for (int m = 0; m < 16; m++) acc2[m] = 0ull;
            #pragma unroll
            for (int c = 0; c < COMP; c += 4) {
                float w0 = wkp[(c+0)*HID], w1 = wkp[(c+1)*HID];
                float w2 = wkp[(c+2)*HID], w3 = wkp[(c+3)*HID];
                u64 w01 = pk(w0, w1), w23 = pk(w2, w3);
                #pragma unroll
                for (int m = 0; m < 16; m++) {
                    u64 a01, a23;
                    lds2(a01, a23, tok_sa + (unsigned)((m * COMP + c) * 4));
                    ffma2(acc2[m], a01, w01); ffma2(acc2[m], a23, w23);
                }
            }
            #pragma unroll
            for (int m = 0; m < 16; m++) kacc[m] += upk_sum(acc2[m]);
        }

        // Phase 2: e = exp(-(Q*K)); write e*V to ha_s; per-row partial sums
        #pragma unroll
        for (int m = 0; m < 16; m++) {
            float e = __expf(-(Qr[m] * (kacc[m] * NF)));
            ha_s[m * HID + t] = e * Vr[m];
            float s = e;
            #pragma unroll
            for (int o = 16; o; o >>= 1) s += __shfl_xor_sync(0xffffffffu, s, o);
            if (l == 0) part_s[m * 8 + w] = s;
        }
        __syncthreads();   // B: ha_s + part_s visible

        // Phase 3a: raw (e*V) @ [Wmu|Wvar], packed FFMA2; thread owns 1 output
        // col for all 16 rows over a 64-wide k-partition (weights LDG x16 reuse)
        {
            const int c  = t & 63;
            const int kp = t >> 6;
            const float* Wcol = (c < 32) ? (Wmu + c) : (Wvar + (c - 32));
            const int k0 = kp * 64;
            u64 acc2[16];
            #pragma unroll
            for (int m = 0; m < 16; m++) acc2[m] = 0ull;
            #pragma unroll 2
            for (int k = k0; k < k0 + 64; k += 4) {
                float w0 = Wcol[(size_t)(k+0)*COMP], w1 = Wcol[(size_t)(k+1)*COMP];
                float w2 = Wcol[(size_t)(k+2)*COMP], w3 = Wcol[(size_t)(k+3)*COMP];
                u64 w01 = pk(w0, w1), w23 = pk(w2, w3);
                #pragma unroll
                for (int m = 0; m < 16; m++) {
                    u64 a01, a23;
                    lds2(a01, a23, ha_sa + (unsigned)((m * HID + k) * 4));
                    ffma2(acc2[m], a01, w01); ffma2(acc2[m], a23, w23);
                }
            }
            __syncthreads();   // D: all ha_s reads done -> reuse as staging
            #pragma unroll
            for (int m = 0; m < 16; m++)
                ha_s[kp * 1024 + m * 64 + c] = upk_sum(acc2[m]);
        }
        __syncthreads();   // E: staging visible

        // Phase 3b+4 merged: kp-reduce + normalize + sample + nearest-vocab,
        // then EOS/repeat-hit via HALF-WARP shfls (row m = 16 lanes), no barrier
        {
            const int m  = t >> 4;
            const int q  = t & 15;
            const int q2 = q * 2;
            float smu0 = 0.0f, smu1 = 0.0f, slv0 = 0.0f, slv1 = 0.0f;
            #pragma unroll
            for (int kp = 0; kp < 4; kp++) {
                float2 a = *(const float2*)&ha_s[kp * 1024 + m * 64 + q2];
                float2 b = *(const float2*)&ha_s[kp * 1024 + m * 64 + 32 + q2];
                smu0 += a.x; smu1 += a.y;
                slv0 += b.x; slv1 += b.y;
            }
            float rs = 0.0f;
            #pragma unroll
            for (int ww = 0; ww < 8; ww++) rs += part_s[m * 8 + ww];
            const float iv = 1.0f / rs;
            float2 bm = *(const float2*)&bmu[q2];
            float2 bv = *(const float2*)&bvar[q2];
            float mu0 = smu0 * iv + bm.x, mu1 = smu1 * iv + bm.y;
            float lv0 = slv0 * iv + bv.x, lv1 = slv1 * iv + bv.y;
            const size_t r = (size_t)(r0 + m);
            float2 e2 = *(const float2*)&eps[((size_t)it * B_ROWS + r) * COMP + q2];
            float x0 = e2.x * __expf(0.5f * lv0) + mu0;
            float x1 = e2.y * __expf(0.5f * lv1) + mu1;
            const float mk = maskf[m];
            float t0 = nearest_sq(vocs_s + q2 * VSTRIDE, x0) * mk;
            float t1 = nearest_sq(vocs_s + (q2 + 1) * VSTRIDE, x1) * mk;

            // EOS hit (half-warp reduce over 16 lanes x 2 comps)
            float2 ev = *(const float2*)&eos_s[q2];
            float de0 = t0 - ev.x, de1 = t1 - ev.y;
            float se = de0 * de0 + de1 * de1;
            #pragma unroll
            for (int o = 8; o; o >>= 1) se += __shfl_xor_sync(0xffffffffu, se, o);
            bool hit = (se < EPS_THR);
            // previous-token hits
            for (int p = 0; p < it; p++) {
                float2 mp = *(const float2*)&msg_s[m * HID + p * COMP + q2];
                float d0 = t0 - mp.x, d1 = t1 - mp.y;
                float sp = d0 * d0 + d1 * d1;
                #pragma unroll
                for (int o = 8; o; o >>= 1) sp += __shfl_xor_sync(0xffffffffu, sp, o);
                hit = hit || (sp < EPS_THR);
            }
            float fin = fin_s[m];
            bool new_eos = hit && (fin == 0.0f);
            float o0 = new_eos ? ev.x : t0;
            float o1 = new_eos ? ev.y : t1;
            *(float2*)&msg_s[m * HID + it * COMP + q2] = make_float2(o0, o1);
            *(float2*)&tok_s[m * COMP + q2] = make_float2(o0, o1);
            if (q == 0 && hit) { maskf[m] = 0.0f; fin_s[m] = 1.0f; }
        }
    }

    // ---- flush message to global for the tail ----
    __syncthreads();
    {
        float4* dst = (float4*)(g_msg + (size_t)r0 * HID);
        const float4* src = (const float4*)msg_s;
        #pragma unroll
        for (int i = 0; i < 4; i++) dst[t + i * 256] = src[t + i * 256];
    }
}

// ---------------- Kernel 2: fused tail: group-sum/7 @Wsum -> @Whead+relu ---
// Two GEMMs, 4 groups/block, grid 512 (~3.5 blocks/SM so weight-LDG latency
// is covered by resident blocks; the R8-profiled 8-group version was
// grid-starved at 1.7 blocks/SM).
__global__ __launch_bounds__(256) void tail_kernel(
    const float* __restrict__ Wsum, const float* __restrict__ bsum,
    const float* __restrict__ Whead, const float* __restrict__ bhead,
    float* __restrict__ out)
{
    __shared__ __align__(16) float A_s[4 * HID];
    const int t = threadIdx.x;
    const int g0 = blockIdx.x * 4;
    const unsigned A_sa = (unsigned)__cvta_generic_to_shared(A_s);

    #pragma unroll
    for (int m = 0; m < 4; m++) {
        float s = 0.0f;
        #pragma unroll
        for (int a = 0; a < 8; a++)
            s += g_msg[(size_t)((g0 + m) * 8 + a) * HID + t];
        A_s[m * HID + t] = s * (1.0f / 7.0f);
    }
    __syncthreads();

    float res[4];
    {
        u64 acc2[4];
        const float bb = bsum[t];
        #pragma unroll
        for (int m = 0; m < 4; m++) acc2[m] = pk(bb, 0.0f);
        #pragma unroll 4
        for (int k = 0; k < HID; k += 4) {
            float w0 = Wsum[(k+0)*HID+t], w1 = Wsum[(k+1)*HID+t];
            float w2 = Wsum[(k+2)*HID+t], w3 = Wsum[(k+3)*HID+t];
            u64 w01 = pk(w0, w1), w23 = pk(w2, w3);
            #pragma unroll
            for (int m = 0; m < 4; m++) {
                u64 a01, a23;
                lds2(a01, a23, A_sa + (unsigned)((m * HID + k) * 4));
                ffma2(acc2[m], a01, w01); ffma2(acc2[m], a23, w23);
            }
        }
        #pragma unroll
        for (int m = 0; m < 4; m++) res[m] = upk_sum(acc2[m]);
    }
    __syncthreads();
    #pragma unroll
    for (int m = 0; m < 4; m++) A_s[m * HID + t] = res[m];
    __syncthreads();

    {
        u64 acc2[4];
        const float bb = bhead[t];
        #pragma unroll
        for (int m = 0; m < 4; m++) acc2[m] = pk(bb, 0.0f);
        #pragma unroll 4
        for (int k = 0; k < HID; k += 4) {
            float w0 = Whead[(k+0)*HID+t], w1 = Whead[(k+1)*HID+t];
            float w2 = Whead[(k+2)*HID+t], w3 = Whead[(k+3)*HID+t];
            u64 w01 = pk(w0, w1), w23 = pk(w2, w3);
            #pragma unroll
            for (int m = 0; m < 4; m++) {
                u64 a01, a23;
                lds2(a01, a23, A_sa + (unsigned)((m * HID + k) * 4));
                ffma2(acc2[m], a01, w01); ffma2(acc2[m], a23, w23);
            }
        }
        #pragma unroll
        for (int m = 0; m < 4; m++) res[m] = upk_sum(acc2[m]);
    }
    #pragma unroll
    for (int m = 0; m < 4; m++) {
        float v = fmaxf(res[m], 0.0f);
        #pragma unroll
        for (int a = 0; a < 8; a++)
            out[(size_t)((g0 + m) * 8 + a) * HID + t] = v;
    }
}

// ---------------- launch ---------------------------------------------------
extern "C" void kernel_launch(void* const* d_in, const int* in_sizes, int n_in,
                              void* d_out, int out_size)
{
    const float* hs    = (const float*)d_in[0];
    const float* eps   = (const float*)d_in[1];
    const float* WQ    = (const float*)d_in[2];
    const float* bQ    = (const float*)d_in[3];
    const float* WK    = (const float*)d_in[4];
    const float* bK    = (const float*)d_in[5];
    const float* Wmu   = (const float*)d_in[6];
    const float* bmu   = (const float*)d_in[7];
    const float* Wvar  = (const float*)d_in[8];
    const float* bvar  = (const float*)d_in[9];
    const float* vocab = (const float*)d_in[10];
    const float* Wsum  = (const float*)d_in[11];
    const float* bsum  = (const float*)d_in[12];
    const float* Whead = (const float*)d_in[13];
    const float* bhead = (const float*)d_in[14];
    float* out = (float*)d_out;

    const int smem_main = 17248 * (int)sizeof(float);   // 68992 B
    cudaFuncSetAttribute(main_kernel,
                         cudaFuncAttributeMaxDynamicSharedMemorySize, smem_main);

    sort_kernel<<<COMP, 512>>>(vocab);
    main_kernel<<<B_ROWS / ROWS_PB, 256, smem_main>>>(
        hs, WQ, bQ, WK, bK, Wmu, bmu, Wvar, bvar, vocab, eps);
    tail_kernel<<<NGROUP / 4, 256>>>(Wsum, bsum, Whead, bhead, out);
}